// round 3
// baseline (speedup 1.0000x reference)
#include <cuda_runtime.h>
#include <cstdint>

// FWHT over contiguous groups of 128 fp32 elements.
// 16 lanes per group: each thread holds two float4s of one group, 64 elements
// apart. Stages h=1,2 intra-quad; h=64 intra-thread; h=4,8,16,32 via
// shfl.xor deltas 1,2,4,8 (stay within 16-lane halves; stages commute).
// 4 group-pairs per thread -> 8 front-batched LDG.128 (MLP=8).

#define NP 4  // group-pairs per thread

__global__ void __launch_bounds__(256) fwht128_kernel(
    const float4* __restrict__ in, float4* __restrict__ out)
{
    const unsigned int lane = threadIdx.x & 31u;
    const unsigned int l16  = lane & 15u;
    const unsigned int half = lane >> 4;          // 0: group 2p, 1: group 2p+1
    const unsigned int wid  = threadIdx.x >> 5;   // warp in block
    // each warp owns 8 consecutive groups = 256 float4s
    const unsigned int wbase = (blockIdx.x * 8u + wid) * 256u;

    // Front-batched loads: 8 independent LDG.128 per thread.
    float4 v0[NP], v1[NP];
    #pragma unroll
    for (int p = 0; p < NP; ++p) {
        unsigned int gbase = wbase + (unsigned)p * 64u + half * 32u;
        v0[p] = __ldcs(in + gbase + l16);        // elements 4*l16 .. +3
        v1[p] = __ldcs(in + gbase + l16 + 16u);  // elements 64+4*l16 .. +3
    }

    float lo[NP][4], hi[NP][4];
    #pragma unroll
    for (int p = 0; p < NP; ++p) {
        // stages h=1, h=2 within each quad
        float a0 = v0[p].x + v0[p].y, a1 = v0[p].x - v0[p].y;
        float a2 = v0[p].z + v0[p].w, a3 = v0[p].z - v0[p].w;
        float A0 = a0 + a2, A1 = a1 + a3, A2 = a0 - a2, A3 = a1 - a3;

        float c0 = v1[p].x + v1[p].y, c1 = v1[p].x - v1[p].y;
        float c2 = v1[p].z + v1[p].w, c3 = v1[p].z - v1[p].w;
        float B0 = c0 + c2, B1 = c1 + c3, B2 = c0 - c2, B3 = c1 - c3;

        // stage h=64: intra-thread butterfly between the two quads
        lo[p][0] = A0 + B0; lo[p][1] = A1 + B1; lo[p][2] = A2 + B2; lo[p][3] = A3 + B3;
        hi[p][0] = A0 - B0; hi[p][1] = A1 - B1; hi[p][2] = A2 - B2; hi[p][3] = A3 - B3;
    }

    // stages h=4,8,16,32 -> shfl.xor deltas 1,2,4,8 (within 16-lane halves)
    #pragma unroll
    for (int d = 1; d <= 8; d <<= 1) {
        bool up = (lane & (unsigned)d) != 0u;
        #pragma unroll
        for (int p = 0; p < NP; ++p) {
            #pragma unroll
            for (int k = 0; k < 4; ++k) {
                float q0 = __shfl_xor_sync(0xffffffffu, lo[p][k], d);
                float q1 = __shfl_xor_sync(0xffffffffu, hi[p][k], d);
                lo[p][k] = up ? (q0 - lo[p][k]) : (lo[p][k] + q0);
                hi[p][k] = up ? (q1 - hi[p][k]) : (hi[p][k] + q1);
            }
        }
    }

    const float S = 0.08838834764831845f;  // 1/sqrt(128)
    #pragma unroll
    for (int p = 0; p < NP; ++p) {
        unsigned int gbase = wbase + (unsigned)p * 64u + half * 32u;
        float4 r0, r1;
        r0.x = lo[p][0] * S; r0.y = lo[p][1] * S; r0.z = lo[p][2] * S; r0.w = lo[p][3] * S;
        r1.x = hi[p][0] * S; r1.y = hi[p][1] * S; r1.z = hi[p][2] * S; r1.w = hi[p][3] * S;
        __stcs(out + gbase + l16, r0);
        __stcs(out + gbase + l16 + 16u, r1);
    }
}

extern "C" void kernel_launch(void* const* d_in, const int* in_sizes, int n_in,
                              void* d_out, int out_size)
{
    const float4* x = (const float4*)d_in[0];
    float4* y = (float4*)d_out;
    // 67108864 floats = 16777216 float4s; each block consumes 8 warps * 256 = 2048.
    unsigned int n4 = (unsigned int)(in_sizes[0] / 4);
    unsigned int grid = n4 / 2048u;  // = 8192
    fwht128_kernel<<<grid, 256>>>(x, y);
}

// round 4
// speedup vs baseline: 1.0043x; 1.0043x over previous
#include <cuda_runtime.h>
#include <cstdint>

// FWHT over contiguous groups of 128 fp32 elements.
// 16 lanes per group: each thread holds two float4s of one group, 64 elements
// apart. Stages h=1,2 intra-quad; h=64 intra-thread; h=4,8,16,32 via
// shfl.xor deltas 1,2,4,8. NP=2 group-pairs per thread -> 4 LDG.128 in flight,
// ~32 regs -> 8 CTAs/SM resident.

#define NP 2  // group-pairs per thread

__global__ void __launch_bounds__(256, 8) fwht128_kernel(
    const float4* __restrict__ in, float4* __restrict__ out)
{
    const unsigned int lane = threadIdx.x & 31u;
    const unsigned int l16  = lane & 15u;
    const unsigned int half = lane >> 4;          // 0: group 2p, 1: group 2p+1
    const unsigned int wid  = threadIdx.x >> 5;   // warp in block
    // each warp owns NP*2 = 4 consecutive groups = 128 float4s
    const unsigned int wbase = (blockIdx.x * 8u + wid) * (NP * 64u);

    // Front-batched loads: 4 independent LDG.128 per thread.
    float4 v0[NP], v1[NP];
    #pragma unroll
    for (int p = 0; p < NP; ++p) {
        unsigned int gbase = wbase + (unsigned)p * 64u + half * 32u;
        v0[p] = __ldcs(in + gbase + l16);        // elements 4*l16 .. +3
        v1[p] = __ldcs(in + gbase + l16 + 16u);  // elements 64+4*l16 .. +3
    }

    float lo[NP][4], hi[NP][4];
    #pragma unroll
    for (int p = 0; p < NP; ++p) {
        // stages h=1, h=2 within each quad
        float a0 = v0[p].x + v0[p].y, a1 = v0[p].x - v0[p].y;
        float a2 = v0[p].z + v0[p].w, a3 = v0[p].z - v0[p].w;
        float A0 = a0 + a2, A1 = a1 + a3, A2 = a0 - a2, A3 = a1 - a3;

        float c0 = v1[p].x + v1[p].y, c1 = v1[p].x - v1[p].y;
        float c2 = v1[p].z + v1[p].w, c3 = v1[p].z - v1[p].w;
        float B0 = c0 + c2, B1 = c1 + c3, B2 = c0 - c2, B3 = c1 - c3;

        // stage h=64: intra-thread butterfly between the two quads
        lo[p][0] = A0 + B0; lo[p][1] = A1 + B1; lo[p][2] = A2 + B2; lo[p][3] = A3 + B3;
        hi[p][0] = A0 - B0; hi[p][1] = A1 - B1; hi[p][2] = A2 - B2; hi[p][3] = A3 - B3;
    }

    // stages h=4,8,16,32 -> shfl.xor deltas 1,2,4,8 (within 16-lane halves)
    #pragma unroll
    for (int d = 1; d <= 8; d <<= 1) {
        bool up = (lane & (unsigned)d) != 0u;
        #pragma unroll
        for (int p = 0; p < NP; ++p) {
            #pragma unroll
            for (int k = 0; k < 4; ++k) {
                float q0 = __shfl_xor_sync(0xffffffffu, lo[p][k], d);
                float q1 = __shfl_xor_sync(0xffffffffu, hi[p][k], d);
                lo[p][k] = up ? (q0 - lo[p][k]) : (lo[p][k] + q0);
                hi[p][k] = up ? (q1 - hi[p][k]) : (hi[p][k] + q1);
            }
        }
    }

    const float S = 0.08838834764831845f;  // 1/sqrt(128)
    #pragma unroll
    for (int p = 0; p < NP; ++p) {
        unsigned int gbase = wbase + (unsigned)p * 64u + half * 32u;
        float4 r0, r1;
        r0.x = lo[p][0] * S; r0.y = lo[p][1] * S; r0.z = lo[p][2] * S; r0.w = lo[p][3] * S;
        r1.x = hi[p][0] * S; r1.y = hi[p][1] * S; r1.z = hi[p][2] * S; r1.w = hi[p][3] * S;
        __stcs(out + gbase + l16, r0);
        __stcs(out + gbase + l16 + 16u, r1);
    }
}

extern "C" void kernel_launch(void* const* d_in, const int* in_sizes, int n_in,
                              void* d_out, int out_size)
{
    const float4* x = (const float4*)d_in[0];
    float4* y = (float4*)d_out;
    // 67108864 floats = 16777216 float4s; each block consumes 8 warps * 128 = 1024.
    unsigned int n4 = (unsigned int)(in_sizes[0] / 4);
    unsigned int grid = n4 / (8u * NP * 64u);  // = 16384
    fwht128_kernel<<<grid, 256>>>(x, y);
}